// round 14
// baseline (speedup 1.0000x reference)
#include <cuda_runtime.h>

#define BATCH 8
#define HW    4096
#define CH    512
#define NMASK 1024
#define NCTX  3072
#define EPSF  1e-8f
#define NSPLIT 4

// ---------------- scratch ----------------------------------------------------
__device__ float g_Am[BATCH * CH * NMASK];            // [b][k][i]
__device__ float g_Amd[BATCH * CH * 2 * NMASK];       // A duplicated: [..][2i]=[..][2i+1]
__device__ float g_Bn[BATCH * CH * NCTX];             // [b][k][j]
__device__ float g_best[BATCH * NMASK * CH];
__device__ float g_mskn[BATCH * NMASK * CH];
__device__ float g_gen[BATCH * NMASK * CH];
__device__ float g_part[NSPLIT][BATCH * HW];
__device__ float g_invall[BATCH * HW];
__device__ float g_n2[BATCH * HW];
__device__ float g_invc[BATCH * NCTX];
__device__ float g_invm[BATCH * NMASK];
__device__ float g_maxc[BATCH * NMASK];
__device__ float g_bn2[BATCH * NMASK];
__device__ unsigned long long g_packed[BATCH * NMASK];
__device__ int   g_imask[HW];

// ---------------- helpers ----------------------------------------------------
__device__ __forceinline__ void cp16(void* sdst, const void* gsrc) {
    unsigned saddr = (unsigned)__cvta_generic_to_shared(sdst);
    asm volatile("cp.async.ca.shared.global [%0], [%1], 16;\n" :: "r"(saddr), "l"(gsrc));
}
__device__ __forceinline__ unsigned ford(float f) {
    unsigned u = __float_as_uint(f);
    return (u & 0x80000000u) ? ~u : (u | 0x80000000u);
}
__device__ __forceinline__ float frcp(float x) {
    float r; asm("rcp.approx.f32 %0, %1;" : "=f"(r) : "f"(x)); return r;
}
__device__ __forceinline__ float frsq(float x) {
    float r; asm("rsqrt.approx.f32 %0, %1;" : "=f"(r) : "f"(x)); return r;
}
__device__ __forceinline__ void st_release_s32(volatile int* p, int v) {
    unsigned a = (unsigned)__cvta_generic_to_shared((void*)p);
    asm volatile("st.release.cta.shared.b32 [%0], %1;" :: "r"(a), "r"(v) : "memory");
}
__device__ __forceinline__ int ld_acquire_s32(volatile int* p) {
    unsigned a = (unsigned)__cvta_generic_to_shared((void*)p);
    int v;
    asm volatile("ld.acquire.cta.shared.b32 %0, [%1];" : "=r"(v) : "r"(a) : "memory");
    return v;
}

// ---------------- K1a/K1b: column norms -------------------------------------
__global__ void k_part(const float* __restrict__ x) {
    int p = blockIdx.x * 256 + threadIdx.x;
    int b = blockIdx.y;
    int z = blockIdx.z;
    const float* base = x + ((size_t)b * CH + (size_t)z * (CH / NSPLIT)) * HW + p;
    float s = 0.f;
#pragma unroll 8
    for (int c = 0; c < CH / NSPLIT; c++) {
        float v = base[(size_t)c * HW];
        s += v * v;
    }
    g_part[z][b * HW + p] = s;
}
__global__ void k_invall() {
    int i = blockIdx.x * 256 + threadIdx.x;
    float s = g_part[0][i] + g_part[1][i] + g_part[2][i] + g_part[3][i];
    g_n2[i] = s;
    g_invall[i] = 1.f / (sqrtf(s) + EPSF);
}

// ---------------- K2: setup --------------------------------------------------
__global__ void k_setup(const int* __restrict__ np, const int* __restrict__ mp) {
    int t = threadIdx.x;  // 1024, 1 block
    for (int p = t; p < HW; p += 1024) g_imask[p] = -1;
    __syncthreads();
    g_imask[mp[t]] = t;
    for (int i = t; i < BATCH * NMASK; i += 1024) g_packed[i] = 0ull;
    for (int i = t; i < BATCH * NMASK; i += 1024) {
        int b = i / NMASK;
        g_invm[i] = g_invall[b * HW + mp[i % NMASK]];
    }
    for (int j = t; j < BATCH * NCTX; j += 1024) {
        int b = j / NCTX;
        g_invc[j] = g_invall[b * HW + np[j % NCTX]];
    }
}

// ---------------- K3: gather A/B (A also duplicated), K-major ----------------
__global__ void k_gather(const float* __restrict__ x,
                         const int* __restrict__ np, const int* __restrict__ mp) {
    int k = blockIdx.x;
    int b = blockIdx.y;
    int t = threadIdx.x;        // 1024
    const float* row = x + ((size_t)b * CH + k) * HW;
    float v = row[mp[t]];
    size_t oa = ((size_t)b * CH + k) * NMASK + t;
    g_Am[oa] = v;
    float2 dv; dv.x = v; dv.y = v;
    *(float2*)&g_Amd[2 * oa] = dv;
#pragma unroll
    for (int j = t; j < NCTX; j += 1024)
        g_Bn[((size_t)b * CH + k) * NCTX + j] = row[np[j]];
}

// ---------------- K4: fp32 GEMM (A pre-duplicated, zero-mov FFMA2 loop) -----
#define BM 128
#define BN 128
#define BK 16
#define NT (CH / BK)

__global__ void __launch_bounds__(256, 2) k_gemm() {
    __shared__ __align__(16) float As[2][BK][2 * BM];   // 32KB (dup pairs)
    __shared__ __align__(16) float Bs[2][BK][BN];       // 16KB

    int b  = blockIdx.z;
    int i0 = blockIdx.y * BM;
    int j0 = blockIdx.x * BN;
    int tid = threadIdx.x;
    int tx = tid & 15, ty = tid >> 4;
    int cA = tx * 4;

    const float* Ad = g_Amd + (size_t)b * CH * 2 * NMASK + 2 * i0;
    const float* Bp = g_Bn  + (size_t)b * CH * NCTX  + j0;

    unsigned long long acc[8][4];
#pragma unroll
    for (int r = 0; r < 8; r++)
#pragma unroll
        for (int q = 0; q < 4; q++) acc[r][q] = 0ull;

#define COPY_TILE(t)                                                          \
    do {                                                                      \
        int s_ = (t) & 1;                                                     \
        const float* ga = Ad + (size_t)((t) * BK + ty) * (2 * NMASK) + cA;    \
        const float* gb = Bp + (size_t)((t) * BK + ty) * NCTX + cA;           \
        cp16(&As[s_][ty][cA],       ga);                                      \
        cp16(&As[s_][ty][64 + cA],  ga + 64);                                 \
        cp16(&As[s_][ty][128 + cA], ga + 128);                                \
        cp16(&As[s_][ty][192 + cA], ga + 192);                                \
        cp16(&Bs[s_][ty][cA],       gb);                                      \
        cp16(&Bs[s_][ty][64 + cA],  gb + 64);                                 \
        asm volatile("cp.async.commit_group;\n");                             \
    } while (0)

    COPY_TILE(0);
    COPY_TILE(1);

#pragma unroll 1
    for (int t = 0; t < NT; t++) {
        if (t < NT - 1) asm volatile("cp.async.wait_group 1;\n");
        else            asm volatile("cp.async.wait_group 0;\n");
        __syncthreads();
        int s = t & 1;
#pragma unroll
        for (int kk = 0; kk < BK; kk++) {
            // A dup pairs: rows ty*4..ty*4+3 at float offsets 8ty..8ty+7;
            // rows 64+ty*4.. at 128+8ty.. (16-lane broadcast per addr: conflict-free)
            ulonglong2 ad0 = *(const ulonglong2*)&As[s][kk][8 * ty];
            ulonglong2 ad1 = *(const ulonglong2*)&As[s][kk][8 * ty + 4];
            ulonglong2 ad2 = *(const ulonglong2*)&As[s][kk][128 + 8 * ty];
            ulonglong2 ad3 = *(const ulonglong2*)&As[s][kk][128 + 8 * ty + 4];
            ulonglong2 bv0 = *(const ulonglong2*)&Bs[s][kk][tx * 4];
            ulonglong2 bv1 = *(const ulonglong2*)&Bs[s][kk][64 + tx * 4];
            unsigned long long ad[8] = {ad0.x, ad0.y, ad1.x, ad1.y,
                                        ad2.x, ad2.y, ad3.x, ad3.y};
            unsigned long long bq[4] = {bv0.x, bv0.y, bv1.x, bv1.y};
#pragma unroll
            for (int r = 0; r < 8; r++)
#pragma unroll
                for (int q = 0; q < 4; q++)
                    asm("fma.rn.f32x2 %0, %1, %2, %0;"
                        : "+l"(acc[r][q]) : "l"(ad[r]), "l"(bq[q]));
        }
        __syncthreads();
        if (t + 2 < NT) COPY_TILE(t + 2);
    }

    float invc[8];
#pragma unroll
    for (int g = 0; g < 2; g++)
#pragma unroll
        for (int e = 0; e < 4; e++)
            invc[g * 4 + e] = g_invc[b * NCTX + j0 + g * 64 + tx * 4 + e];

#pragma unroll
    for (int r = 0; r < 8; r++) {
        int irow = (r < 4) ? (ty * 4 + r) : (64 + ty * 4 + (r - 4));
        unsigned long long bp = 0ull;
#pragma unroll
        for (int q = 0; q < 4; q++) {
            float lo = __uint_as_float((unsigned)acc[r][q]);
            float hi = __uint_as_float((unsigned)(acc[r][q] >> 32));
            float v0 = lo * invc[q * 2];
            float v1 = hi * invc[q * 2 + 1];
            int jg = j0 + ((q >> 1) * 64) + tx * 4 + (q & 1) * 2;
            unsigned long long p0 = ((unsigned long long)ford(v0) << 32) | (unsigned)(~(unsigned)jg);
            unsigned long long p1 = ((unsigned long long)ford(v1) << 32) | (unsigned)(~(unsigned)(jg + 1));
            if (p0 > bp) bp = p0;
            if (p1 > bp) bp = p1;
        }
#pragma unroll
        for (int o = 1; o < 16; o <<= 1) {
            unsigned long long other = __shfl_xor_sync(0xffffffffu, bp, o);
            if (other > bp) bp = other;
        }
        if (tx == 0) atomicMax(&g_packed[b * NMASK + i0 + irow], bp);
    }
}

// ---------------- K5: finalize pick + gather + |best|^2 ----------------------
__global__ void k_finalize(const int* __restrict__ np) {
    int i = blockIdx.x;
    int b = blockIdx.y;
    int t = threadIdx.x;  // 256
    __shared__ int s_j;
    __shared__ float s_invm;
    if (t == 0) {
        unsigned long long pk = g_packed[b * NMASK + i];
        unsigned j  = ~(unsigned)pk;
        unsigned ov = (unsigned)(pk >> 32);
        unsigned fb = (ov & 0x80000000u) ? (ov & 0x7fffffffu) : ~ov;
        float val = __uint_as_float(fb);
        float im  = g_invm[b * NMASK + i];
        g_maxc[b * NMASK + i] = val * im;
        g_bn2[b * NMASK + i] = g_n2[b * HW + np[j]];
        s_j = (int)j;
        s_invm = im;
    }
    __syncthreads();
    int jj = s_j;
    float im = s_invm;
    const float* Am = g_Am + (size_t)b * CH * NMASK;
    const float* Bn = g_Bn + (size_t)b * CH * NCTX;
    size_t o = ((size_t)b * NMASK + i) * CH;
#pragma unroll
    for (int c = t; c < CH; c += 256) {
        g_best[o + c] = Bn[(size_t)c * NCTX + jj];
        g_mskn[o + c] = Am[(size_t)c * NMASK + i] * im;
    }
}

// ---------------- K6: scan v5 — conflict-free interleaved ring ---------------
#define NRING 16
#define NG (NMASK / 4)

struct ScanState { float s1, rnd; };

__device__ __forceinline__ void scan_step(
    int i, float mx, float bn2, float* q, ScanState& st,
    const float (*ring)[2][CH], float* GE, int lane)
{
    int s = i & (NRING - 1);
    float mn[16], bs[16];
#pragma unroll
    for (int u = 0; u < 4; u++) {
        float4 a = *(const float4*)&ring[s][0][u * 128 + lane * 4];
        mn[u*4+0]=a.x; mn[u*4+1]=a.y; mn[u*4+2]=a.z; mn[u*4+3]=a.w;
        float4 c = *(const float4*)&ring[s][1][u * 128 + lane * 4];
        bs[u*4+0]=c.x; bs[u*4+1]=c.y; bs[u*4+2]=c.z; bs[u*4+3]=c.w;
    }
    float p2[8], pc[8];
#pragma unroll
    for (int e = 0; e < 8; e++) {
        p2[e] = __fmaf_rn(mn[e], q[e], mn[e + 8] * q[e + 8]);
        pc[e] = __fmaf_rn(bs[e], q[e], bs[e + 8] * q[e + 8]);
    }
#pragma unroll
    for (int w = 4; w; w >>= 1)
#pragma unroll
        for (int e = 0; e < w; e++) { p2[e] += p2[e + w]; pc[e] += pc[e + w]; }
    float s2 = p2[0], c = pc[0];
#pragma unroll
    for (int o = 16; o; o >>= 1) {
        s2 += __shfl_xor_sync(0xffffffffu, s2, o);
        c  += __shfl_xor_sync(0xffffffffu, c,  o);
    }
    float s2p = fmaxf(s2, 0.f);
    float d   = s2p * st.rnd;
    float T   = d + mx + EPSF;
    float rT  = frcp(T);
    float w1 = d * rT, w2 = mx * rT;
#pragma unroll
    for (int e = 0; e < 16; e++) q[e] = __fmaf_rn(w1, q[e], w2 * bs[e]);
    float* ge = GE + (size_t)i * CH + lane * 16;
#pragma unroll
    for (int u = 0; u < 4; u++) {
        float4 w;
        w.x = q[u*4+0]; w.y = q[u*4+1]; w.z = q[u*4+2]; w.w = q[u*4+3];
        *(float4*)(ge + u * 4) = w;
    }
    float aa = w1 * w1, ab = w1 * w2, bb = w2 * w2;
    st.s1 = __fmaf_rn(aa, st.s1, __fmaf_rn(2.f * ab, c, bb * bn2));
    float rs  = (st.s1 > 0.f) ? frsq(st.s1) : 0.f;
    float nrm = st.s1 * rs;
    st.rnd = frcp(nrm + EPSF);
}

__global__ void __launch_bounds__(64, 1) k_scan() {
    __shared__ __align__(16) float ring[NRING][2][CH];   // 64KB
    __shared__ int rflag, cdone;

    int b = blockIdx.x;
    int warp = threadIdx.x >> 5;
    int lane = threadIdx.x & 31;

    const float* MN  = g_mskn + (size_t)b * NMASK * CH;
    const float* BS  = g_best + (size_t)b * NMASK * CH;
    float*       GE  = g_gen  + (size_t)b * NMASK * CH;
    const float* MX  = g_maxc + b * NMASK;
    const float* BN2 = g_bn2  + b * NMASK;

    if (threadIdx.x == 0) { rflag = -1; cdone = -1; }
    __syncthreads();

#define PRE(i, s)                                                             \
    do {                                                                      \
        const float* pm = MN + (size_t)(i) * CH + lane * 16;                  \
        const float* pb = BS + (size_t)(i) * CH + lane * 16;                  \
        cp16(&ring[s][0][0 * 128 + lane * 4], pm);                            \
        cp16(&ring[s][0][1 * 128 + lane * 4], pm + 4);                        \
        cp16(&ring[s][0][2 * 128 + lane * 4], pm + 8);                        \
        cp16(&ring[s][0][3 * 128 + lane * 4], pm + 12);                       \
        cp16(&ring[s][1][0 * 128 + lane * 4], pb);                            \
        cp16(&ring[s][1][1 * 128 + lane * 4], pb + 4);                        \
        cp16(&ring[s][1][2 * 128 + lane * 4], pb + 8);                        \
        cp16(&ring[s][1][3 * 128 + lane * 4], pb + 12);                       \
    } while (0)

    if (warp == 1) {
        // producer
#pragma unroll
        for (int g = 0; g < 4; g++) {
#pragma unroll
            for (int k = 0; k < 4; k++) PRE(4 * g + k, (4 * g + k) & (NRING - 1));
            asm volatile("cp.async.commit_group;\n");
        }
#pragma unroll 1
        for (int g = 0; g < NG; g++) {
            int rem = NG - 1 - g;
            if (rem >= 3)      asm volatile("cp.async.wait_group 3;\n");
            else if (rem == 2) asm volatile("cp.async.wait_group 2;\n");
            else if (rem == 1) asm volatile("cp.async.wait_group 1;\n");
            else               asm volatile("cp.async.wait_group 0;\n");
            __syncwarp();
            if (lane == 0) st_release_s32(&rflag, 4 * g + 3);
            if (g + 4 < NG) {
                while (ld_acquire_s32(&cdone) < 4 * g + 3) { }
                int s0 = 4 * (g + 4);
#pragma unroll
                for (int k = 0; k < 4; k++) PRE(s0 + k, (s0 + k) & (NRING - 1));
                asm volatile("cp.async.commit_group;\n");
            }
        }
    } else {
        // consumer
        float q[16];
#pragma unroll
        for (int e = 0; e < 16; e++) q[e] = 0.f;
        ScanState st;
        st.s1 = 0.f;
        st.rnd = frcp(EPSF);
        int ready = -1;
        float4 mx4 = *(const float4*)MX;
        float4 b24 = *(const float4*)BN2;

#pragma unroll 1
        for (int g = 0; g < NG; g++) {
            int i0 = g * 4;
            if (ready < i0 + 3) {
                do { ready = ld_acquire_s32(&rflag); } while (ready < i0 + 3);
            }
            float4 mx4n = mx4, b24n = b24;
            if (g + 1 < NG) {
                mx4n = *(const float4*)(MX + i0 + 4);
                b24n = *(const float4*)(BN2 + i0 + 4);
            }
            scan_step(i0 + 0, mx4.x, b24.x, q, st, ring, GE, lane);
            scan_step(i0 + 1, mx4.y, b24.y, q, st, ring, GE, lane);
            scan_step(i0 + 2, mx4.z, b24.z, q, st, ring, GE, lane);
            scan_step(i0 + 3, mx4.w, b24.w, q, st, ring, GE, lane);
            mx4 = mx4n; b24 = b24n;
            __syncwarp();
            if (lane == 0) st_release_s32(&cdone, i0 + 3);
        }
    }
}

// ---------------- K7: assemble output ---------------------------------------
__global__ void k_out(const float* __restrict__ x, float* __restrict__ out) {
    int idx = blockIdx.x * 256 + threadIdx.x;
    int p = idx & (HW - 1);
    int c = (idx >> 12) & (CH - 1);
    int b = idx >> 21;
    int mi = g_imask[p];
    float v = (mi >= 0) ? g_gen[(((size_t)b * NMASK) + mi) * CH + c] : x[idx];
    out[idx] = v;
}

// ---------------- launch -----------------------------------------------------
extern "C" void kernel_launch(void* const* d_in, const int* in_sizes, int n_in,
                              void* d_out, int out_size) {
    const float* x  = (const float*)d_in[0];
    const int*   np = (const int*)d_in[2];
    const int*   mp = (const int*)d_in[3];
    float*       out = (float*)d_out;

    k_part    <<<dim3(HW / 256, BATCH, NSPLIT), 256>>>(x);
    k_invall  <<<BATCH * HW / 256, 256>>>();
    k_setup   <<<1, 1024>>>(np, mp);
    k_gather  <<<dim3(CH, BATCH), 1024>>>(x, np, mp);
    k_gemm    <<<dim3(NCTX / BN, NMASK / BM, BATCH), 256>>>();
    k_finalize<<<dim3(NMASK, BATCH), 256>>>(np);
    k_scan    <<<BATCH, 64>>>();
    k_out     <<<(BATCH * CH * HW) / 256, 256>>>(x, out);
}

// round 15
// speedup vs baseline: 1.0143x; 1.0143x over previous
#include <cuda_runtime.h>

#define BATCH 8
#define HW    4096
#define CH    512
#define NMASK 1024
#define NCTX  3072
#define EPSF  1e-8f
#define NSPLIT 4

// ---------------- scratch ----------------------------------------------------
__device__ float g_Am[BATCH * CH * NMASK];            // [b][k][i]
__device__ float g_Bn[BATCH * CH * NCTX];             // [b][k][j]
__device__ float g_best[BATCH * NMASK * CH];
__device__ float g_mskn[BATCH * NMASK * CH];
__device__ float g_gen[BATCH * NMASK * CH];
__device__ float g_part[NSPLIT][BATCH * HW];
__device__ float g_invall[BATCH * HW];
__device__ float g_n2[BATCH * HW];
__device__ float g_invc[BATCH * NCTX];
__device__ float g_invm[BATCH * NMASK];
__device__ float g_maxc[BATCH * NMASK];
__device__ float g_bn2[BATCH * NMASK];
__device__ unsigned long long g_packed[BATCH * NMASK];
__device__ int   g_imask[HW];

// ---------------- helpers ----------------------------------------------------
__device__ __forceinline__ void cp16(void* sdst, const void* gsrc) {
    unsigned saddr = (unsigned)__cvta_generic_to_shared(sdst);
    asm volatile("cp.async.ca.shared.global [%0], [%1], 16;\n" :: "r"(saddr), "l"(gsrc));
}
__device__ __forceinline__ unsigned ford(float f) {
    unsigned u = __float_as_uint(f);
    return (u & 0x80000000u) ? ~u : (u | 0x80000000u);
}
__device__ __forceinline__ float frcp(float x) {
    float r; asm("rcp.approx.f32 %0, %1;" : "=f"(r) : "f"(x)); return r;
}
__device__ __forceinline__ float frsq(float x) {
    float r; asm("rsqrt.approx.f32 %0, %1;" : "=f"(r) : "f"(x)); return r;
}
__device__ __forceinline__ void st_release_s32(volatile int* p, int v) {
    unsigned a = (unsigned)__cvta_generic_to_shared((void*)p);
    asm volatile("st.release.cta.shared.b32 [%0], %1;" :: "r"(a), "r"(v) : "memory");
}
__device__ __forceinline__ int ld_acquire_s32(volatile int* p) {
    unsigned a = (unsigned)__cvta_generic_to_shared((void*)p);
    int v;
    asm volatile("ld.acquire.cta.shared.b32 %0, [%1];" : "=r"(v) : "r"(a) : "memory");
    return v;
}

// ---------------- K1a/K1b: column norms -------------------------------------
__global__ void k_part(const float* __restrict__ x) {
    int p = blockIdx.x * 256 + threadIdx.x;
    int b = blockIdx.y;
    int z = blockIdx.z;
    const float* base = x + ((size_t)b * CH + (size_t)z * (CH / NSPLIT)) * HW + p;
    float s = 0.f;
#pragma unroll 8
    for (int c = 0; c < CH / NSPLIT; c++) {
        float v = base[(size_t)c * HW];
        s += v * v;
    }
    g_part[z][b * HW + p] = s;
}
__global__ void k_invall() {
    int i = blockIdx.x * 256 + threadIdx.x;
    float s = g_part[0][i] + g_part[1][i] + g_part[2][i] + g_part[3][i];
    g_n2[i] = s;
    g_invall[i] = 1.f / (sqrtf(s) + EPSF);
}

// ---------------- K2: setup --------------------------------------------------
__global__ void k_setup(const int* __restrict__ np, const int* __restrict__ mp) {
    int t = threadIdx.x;  // 1024, 1 block
    for (int p = t; p < HW; p += 1024) g_imask[p] = -1;
    __syncthreads();
    g_imask[mp[t]] = t;
    for (int i = t; i < BATCH * NMASK; i += 1024) g_packed[i] = 0ull;
    for (int i = t; i < BATCH * NMASK; i += 1024) {
        int b = i / NMASK;
        g_invm[i] = g_invall[b * HW + mp[i % NMASK]];
    }
    for (int j = t; j < BATCH * NCTX; j += 1024) {
        int b = j / NCTX;
        g_invc[j] = g_invall[b * HW + np[j % NCTX]];
    }
}

// ---------------- K3: gather A/B, K-major ------------------------------------
__global__ void k_gather(const float* __restrict__ x,
                         const int* __restrict__ np, const int* __restrict__ mp) {
    int k = blockIdx.x;
    int b = blockIdx.y;
    int t = threadIdx.x;        // 1024
    const float* row = x + ((size_t)b * CH + k) * HW;
    g_Am[((size_t)b * CH + k) * NMASK + t] = row[mp[t]];
#pragma unroll
    for (int j = t; j < NCTX; j += 1024)
        g_Bn[((size_t)b * CH + k) * NCTX + j] = row[np[j]];
}

// ---------------- K4: fp32 GEMM — 4x16 thread tile, interleaved B smem -------
// Thread tile: 4 A rows (broadcast; 4 movs) x 16 B cols (8 FFMA2 pairs).
// B smem layout per k-row: [c][tx][4] (col j = tx*16 + 4c + e at word c*32+tx*4+e)
// -> both cp.async STS and LDS.128 conflict-free.
#define BM 128
#define BN 128
#define BK 16
#define NT (CH / BK)

__global__ void __launch_bounds__(256, 2) k_gemm() {
    __shared__ __align__(16) float As[2][BK][BM];
    __shared__ __align__(16) float Bs[2][BK][BN];

    int b  = blockIdx.z;
    int i0 = blockIdx.y * BM;
    int j0 = blockIdx.x * BN;
    int tid = threadIdx.x;
    int tx0 = tid & 15, ty0 = tid >> 4;    // copy-phase roles (16 x 16)
    int tx = tid & 7,  ty = tid >> 3;      // compute roles (8 cols-groups x 32 row-groups)
    int cA = tx0 * 4;

    const float* A  = g_Am + (size_t)b * CH * NMASK + i0;
    const float* Bp = g_Bn + (size_t)b * CH * NCTX  + j0;

    // B interleave: chunk g (cols 4g..4g+3) -> word (g&3)*32 + (g>>2)*4
    int bdst0 = (tx0 & 3) * 32 + (tx0 >> 2) * 4;

    unsigned long long acc[4][8];
#pragma unroll
    for (int r = 0; r < 4; r++)
#pragma unroll
        for (int q = 0; q < 8; q++) acc[r][q] = 0ull;

#define COPY_TILE(t)                                                          \
    do {                                                                      \
        int s_ = (t) & 1;                                                     \
        const float* ga = A  + (size_t)((t) * BK + ty0) * NMASK + cA;         \
        const float* gb = Bp + (size_t)((t) * BK + ty0) * NCTX  + 4 * tx0;    \
        cp16(&As[s_][ty0][cA],      ga);                                      \
        cp16(&As[s_][ty0][64 + cA], ga + 64);                                 \
        cp16(&Bs[s_][ty0][bdst0],      gb);                                   \
        cp16(&Bs[s_][ty0][bdst0 + 16], gb + 64);                              \
        asm volatile("cp.async.commit_group;\n");                             \
    } while (0)

    COPY_TILE(0);
    COPY_TILE(1);

#pragma unroll 1
    for (int t = 0; t < NT; t++) {
        if (t < NT - 1) asm volatile("cp.async.wait_group 1;\n");
        else            asm volatile("cp.async.wait_group 0;\n");
        __syncthreads();
        int s = t & 1;
#pragma unroll
        for (int kk = 0; kk < BK; kk++) {
            float4 av = *(const float4*)&As[s][kk][ty * 4];
            ulonglong2 bv0 = *(const ulonglong2*)&Bs[s][kk][tx * 4];
            ulonglong2 bv1 = *(const ulonglong2*)&Bs[s][kk][32 + tx * 4];
            ulonglong2 bv2 = *(const ulonglong2*)&Bs[s][kk][64 + tx * 4];
            ulonglong2 bv3 = *(const ulonglong2*)&Bs[s][kk][96 + tx * 4];
            float ar[4] = {av.x, av.y, av.z, av.w};
            unsigned long long bq[8] = {bv0.x, bv0.y, bv1.x, bv1.y,
                                        bv2.x, bv2.y, bv3.x, bv3.y};
#pragma unroll
            for (int r = 0; r < 4; r++) {
                unsigned long long a2;
                asm("mov.b64 %0, {%1, %1};" : "=l"(a2) : "r"(__float_as_uint(ar[r])));
#pragma unroll
                for (int q = 0; q < 8; q++)
                    asm("fma.rn.f32x2 %0, %1, %2, %0;"
                        : "+l"(acc[r][q]) : "l"(a2), "l"(bq[q]));
            }
        }
        __syncthreads();
        if (t + 2 < NT) COPY_TILE(t + 2);
    }

    // epilogue: thread owns rows ty*4+r, cols j0 + tx*16 + 2q (+1)
    float invc[16];
#pragma unroll
    for (int c = 0; c < 4; c++) {
        float4 iv = *(const float4*)&g_invc[b * NCTX + j0 + tx * 16 + 4 * c];
        invc[4 * c + 0] = iv.x; invc[4 * c + 1] = iv.y;
        invc[4 * c + 2] = iv.z; invc[4 * c + 3] = iv.w;
    }

#pragma unroll
    for (int r = 0; r < 4; r++) {
        int irow = ty * 4 + r;
        unsigned long long bp = 0ull;
#pragma unroll
        for (int q = 0; q < 8; q++) {
            float lo = __uint_as_float((unsigned)acc[r][q]);
            float hi = __uint_as_float((unsigned)(acc[r][q] >> 32));
            float v0 = lo * invc[2 * q];
            float v1 = hi * invc[2 * q + 1];
            int jg = j0 + tx * 16 + 2 * q;
            unsigned long long p0 = ((unsigned long long)ford(v0) << 32) | (unsigned)(~(unsigned)jg);
            unsigned long long p1 = ((unsigned long long)ford(v1) << 32) | (unsigned)(~(unsigned)(jg + 1));
            if (p0 > bp) bp = p0;
            if (p1 > bp) bp = p1;
        }
        // reduce across the 8 tx-lanes sharing this row (consecutive lanes)
#pragma unroll
        for (int o = 1; o < 8; o <<= 1) {
            unsigned long long other = __shfl_xor_sync(0xffffffffu, bp, o);
            if (other > bp) bp = other;
        }
        if (tx == 0) atomicMax(&g_packed[b * NMASK + i0 + irow], bp);
    }
}

// ---------------- K5: finalize pick + gather + |best|^2 ----------------------
__global__ void k_finalize(const int* __restrict__ np) {
    int i = blockIdx.x;
    int b = blockIdx.y;
    int t = threadIdx.x;  // 256
    __shared__ int s_j;
    __shared__ float s_invm;
    if (t == 0) {
        unsigned long long pk = g_packed[b * NMASK + i];
        unsigned j  = ~(unsigned)pk;
        unsigned ov = (unsigned)(pk >> 32);
        unsigned fb = (ov & 0x80000000u) ? (ov & 0x7fffffffu) : ~ov;
        float val = __uint_as_float(fb);
        float im  = g_invm[b * NMASK + i];
        g_maxc[b * NMASK + i] = val * im;
        g_bn2[b * NMASK + i] = g_n2[b * HW + np[j]];
        s_j = (int)j;
        s_invm = im;
    }
    __syncthreads();
    int jj = s_j;
    float im = s_invm;
    const float* Am = g_Am + (size_t)b * CH * NMASK;
    const float* Bn = g_Bn + (size_t)b * CH * NCTX;
    size_t o = ((size_t)b * NMASK + i) * CH;
#pragma unroll
    for (int c = t; c < CH; c += 256) {
        g_best[o + c] = Bn[(size_t)c * NCTX + jj];
        g_mskn[o + c] = Am[(size_t)c * NMASK + i] * im;
    }
}

// ---------------- K6: scan v5 — conflict-free interleaved ring ---------------
#define NRING 16
#define NG (NMASK / 4)

struct ScanState { float s1, rnd; };

__device__ __forceinline__ void scan_step(
    int i, float mx, float bn2, float* q, ScanState& st,
    const float (*ring)[2][CH], float* GE, int lane)
{
    int s = i & (NRING - 1);
    float mn[16], bs[16];
#pragma unroll
    for (int u = 0; u < 4; u++) {
        float4 a = *(const float4*)&ring[s][0][u * 128 + lane * 4];
        mn[u*4+0]=a.x; mn[u*4+1]=a.y; mn[u*4+2]=a.z; mn[u*4+3]=a.w;
        float4 c = *(const float4*)&ring[s][1][u * 128 + lane * 4];
        bs[u*4+0]=c.x; bs[u*4+1]=c.y; bs[u*4+2]=c.z; bs[u*4+3]=c.w;
    }
    float p2[8], pc[8];
#pragma unroll
    for (int e = 0; e < 8; e++) {
        p2[e] = __fmaf_rn(mn[e], q[e], mn[e + 8] * q[e + 8]);
        pc[e] = __fmaf_rn(bs[e], q[e], bs[e + 8] * q[e + 8]);
    }
#pragma unroll
    for (int w = 4; w; w >>= 1)
#pragma unroll
        for (int e = 0; e < w; e++) { p2[e] += p2[e + w]; pc[e] += pc[e + w]; }
    float s2 = p2[0], c = pc[0];
#pragma unroll
    for (int o = 16; o; o >>= 1) {
        s2 += __shfl_xor_sync(0xffffffffu, s2, o);
        c  += __shfl_xor_sync(0xffffffffu, c,  o);
    }
    float s2p = fmaxf(s2, 0.f);
    float d   = s2p * st.rnd;
    float T   = d + mx + EPSF;
    float rT  = frcp(T);
    float w1 = d * rT, w2 = mx * rT;
#pragma unroll
    for (int e = 0; e < 16; e++) q[e] = __fmaf_rn(w1, q[e], w2 * bs[e]);
    float* ge = GE + (size_t)i * CH + lane * 16;
#pragma unroll
    for (int u = 0; u < 4; u++) {
        float4 w;
        w.x = q[u*4+0]; w.y = q[u*4+1]; w.z = q[u*4+2]; w.w = q[u*4+3];
        *(float4*)(ge + u * 4) = w;
    }
    float aa = w1 * w1, ab = w1 * w2, bb = w2 * w2;
    st.s1 = __fmaf_rn(aa, st.s1, __fmaf_rn(2.f * ab, c, bb * bn2));
    float rs  = (st.s1 > 0.f) ? frsq(st.s1) : 0.f;
    float nrm = st.s1 * rs;
    st.rnd = frcp(nrm + EPSF);
}

__global__ void __launch_bounds__(64, 1) k_scan() {
    __shared__ __align__(16) float ring[NRING][2][CH];   // 64KB
    __shared__ int rflag, cdone;

    int b = blockIdx.x;
    int warp = threadIdx.x >> 5;
    int lane = threadIdx.x & 31;

    const float* MN  = g_mskn + (size_t)b * NMASK * CH;
    const float* BS  = g_best + (size_t)b * NMASK * CH;
    float*       GE  = g_gen  + (size_t)b * NMASK * CH;
    const float* MX  = g_maxc + b * NMASK;
    const float* BN2 = g_bn2  + b * NMASK;

    if (threadIdx.x == 0) { rflag = -1; cdone = -1; }
    __syncthreads();

#define PRE(i, s)                                                             \
    do {                                                                      \
        const float* pm = MN + (size_t)(i) * CH + lane * 16;                  \
        const float* pb = BS + (size_t)(i) * CH + lane * 16;                  \
        cp16(&ring[s][0][0 * 128 + lane * 4], pm);                            \
        cp16(&ring[s][0][1 * 128 + lane * 4], pm + 4);                        \
        cp16(&ring[s][0][2 * 128 + lane * 4], pm + 8);                        \
        cp16(&ring[s][0][3 * 128 + lane * 4], pm + 12);                       \
        cp16(&ring[s][1][0 * 128 + lane * 4], pb);                            \
        cp16(&ring[s][1][1 * 128 + lane * 4], pb + 4);                        \
        cp16(&ring[s][1][2 * 128 + lane * 4], pb + 8);                        \
        cp16(&ring[s][1][3 * 128 + lane * 4], pb + 12);                       \
    } while (0)

    if (warp == 1) {
        // producer
#pragma unroll
        for (int g = 0; g < 4; g++) {
#pragma unroll
            for (int k = 0; k < 4; k++) PRE(4 * g + k, (4 * g + k) & (NRING - 1));
            asm volatile("cp.async.commit_group;\n");
        }
#pragma unroll 1
        for (int g = 0; g < NG; g++) {
            int rem = NG - 1 - g;
            if (rem >= 3)      asm volatile("cp.async.wait_group 3;\n");
            else if (rem == 2) asm volatile("cp.async.wait_group 2;\n");
            else if (rem == 1) asm volatile("cp.async.wait_group 1;\n");
            else               asm volatile("cp.async.wait_group 0;\n");
            __syncwarp();
            if (lane == 0) st_release_s32(&rflag, 4 * g + 3);
            if (g + 4 < NG) {
                while (ld_acquire_s32(&cdone) < 4 * g + 3) { }
                int s0 = 4 * (g + 4);
#pragma unroll
                for (int k = 0; k < 4; k++) PRE(s0 + k, (s0 + k) & (NRING - 1));
                asm volatile("cp.async.commit_group;\n");
            }
        }
    } else {
        // consumer
        float q[16];
#pragma unroll
        for (int e = 0; e < 16; e++) q[e] = 0.f;
        ScanState st;
        st.s1 = 0.f;
        st.rnd = frcp(EPSF);
        int ready = -1;
        float4 mx4 = *(const float4*)MX;
        float4 b24 = *(const float4*)BN2;

#pragma unroll 1
        for (int g = 0; g < NG; g++) {
            int i0 = g * 4;
            if (ready < i0 + 3) {
                do { ready = ld_acquire_s32(&rflag); } while (ready < i0 + 3);
            }
            float4 mx4n = mx4, b24n = b24;
            if (g + 1 < NG) {
                mx4n = *(const float4*)(MX + i0 + 4);
                b24n = *(const float4*)(BN2 + i0 + 4);
            }
            scan_step(i0 + 0, mx4.x, b24.x, q, st, ring, GE, lane);
            scan_step(i0 + 1, mx4.y, b24.y, q, st, ring, GE, lane);
            scan_step(i0 + 2, mx4.z, b24.z, q, st, ring, GE, lane);
            scan_step(i0 + 3, mx4.w, b24.w, q, st, ring, GE, lane);
            mx4 = mx4n; b24 = b24n;
            __syncwarp();
            if (lane == 0) st_release_s32(&cdone, i0 + 3);
        }
    }
}

// ---------------- K7: assemble output ---------------------------------------
__global__ void k_out(const float* __restrict__ x, float* __restrict__ out) {
    int idx = blockIdx.x * 256 + threadIdx.x;
    int p = idx & (HW - 1);
    int c = (idx >> 12) & (CH - 1);
    int b = idx >> 21;
    int mi = g_imask[p];
    float v = (mi >= 0) ? g_gen[(((size_t)b * NMASK) + mi) * CH + c] : x[idx];
    out[idx] = v;
}

// ---------------- launch -----------------------------------------------------
extern "C" void kernel_launch(void* const* d_in, const int* in_sizes, int n_in,
                              void* d_out, int out_size) {
    const float* x  = (const float*)d_in[0];
    const int*   np = (const int*)d_in[2];
    const int*   mp = (const int*)d_in[3];
    float*       out = (float*)d_out;

    k_part    <<<dim3(HW / 256, BATCH, NSPLIT), 256>>>(x);
    k_invall  <<<BATCH * HW / 256, 256>>>();
    k_setup   <<<1, 1024>>>(np, mp);
    k_gather  <<<dim3(CH, BATCH), 1024>>>(x, np, mp);
    k_gemm    <<<dim3(NCTX / BN, NMASK / BM, BATCH), 256>>>();
    k_finalize<<<dim3(NMASK, BATCH), 256>>>(np);
    k_scan    <<<BATCH, 64>>>();
    k_out     <<<(BATCH * CH * HW) / 256, 256>>>(x, out);
}

// round 16
// speedup vs baseline: 1.1076x; 1.0921x over previous
#include <cuda_runtime.h>

#define BATCH 8
#define HW    4096
#define CH    512
#define NMASK 1024
#define NCTX  3072
#define EPSF  1e-8f
#define NSPLIT 4

// ---------------- scratch ----------------------------------------------------
__device__ float g_Am[BATCH * CH * NMASK];            // [b][k][i]
__device__ float g_Bn[BATCH * CH * NCTX];             // [b][k][j]
__device__ float g_best[BATCH * NMASK * CH];
__device__ float g_mskn[BATCH * NMASK * CH];
__device__ float g_gen[BATCH * NMASK * CH];
__device__ float g_part[NSPLIT][BATCH * HW];
__device__ float g_invall[BATCH * HW];
__device__ float g_n2[BATCH * HW];
__device__ float g_invc[BATCH * NCTX];
__device__ float g_invm[BATCH * NMASK];
__device__ float g_maxc[BATCH * NMASK];
__device__ float g_bn2[BATCH * NMASK];
__device__ unsigned long long g_packed[BATCH * NMASK];
__device__ int   g_imask[HW];

// ---------------- helpers ----------------------------------------------------
__device__ __forceinline__ void cp16(void* sdst, const void* gsrc) {
    unsigned saddr = (unsigned)__cvta_generic_to_shared(sdst);
    asm volatile("cp.async.ca.shared.global [%0], [%1], 16;\n" :: "r"(saddr), "l"(gsrc));
}
__device__ __forceinline__ unsigned ford(float f) {
    unsigned u = __float_as_uint(f);
    return (u & 0x80000000u) ? ~u : (u | 0x80000000u);
}
__device__ __forceinline__ float frcp(float x) {
    float r; asm("rcp.approx.f32 %0, %1;" : "=f"(r) : "f"(x)); return r;
}
__device__ __forceinline__ float frsq(float x) {
    float r; asm("rsqrt.approx.f32 %0, %1;" : "=f"(r) : "f"(x)); return r;
}
__device__ __forceinline__ void st_release_s32(volatile int* p, int v) {
    unsigned a = (unsigned)__cvta_generic_to_shared((void*)p);
    asm volatile("st.release.cta.shared.b32 [%0], %1;" :: "r"(a), "r"(v) : "memory");
}
__device__ __forceinline__ int ld_acquire_s32(volatile int* p) {
    unsigned a = (unsigned)__cvta_generic_to_shared((void*)p);
    int v;
    asm volatile("ld.acquire.cta.shared.b32 %0, [%1];" : "=r"(v) : "r"(a) : "memory");
    return v;
}
// f32x2 packed helpers
__device__ __forceinline__ unsigned long long dup2(float v) {
    unsigned long long r;
    asm("mov.b64 %0, {%1, %1};" : "=l"(r) : "r"(__float_as_uint(v)));
    return r;
}
__device__ __forceinline__ unsigned long long fma2(unsigned long long a,
                                                   unsigned long long b,
                                                   unsigned long long c) {
    unsigned long long d;
    asm("fma.rn.f32x2 %0, %1, %2, %3;" : "=l"(d) : "l"(a), "l"(b), "l"(c));
    return d;
}
__device__ __forceinline__ unsigned long long mul2(unsigned long long a,
                                                   unsigned long long b) {
    unsigned long long d;
    asm("mul.rn.f32x2 %0, %1, %2;" : "=l"(d) : "l"(a), "l"(b));
    return d;
}
__device__ __forceinline__ unsigned long long add2(unsigned long long a,
                                                   unsigned long long b) {
    unsigned long long d;
    asm("add.rn.f32x2 %0, %1, %2;" : "=l"(d) : "l"(a), "l"(b));
    return d;
}
__device__ __forceinline__ float hsum2(unsigned long long v) {
    unsigned lo, hi;
    asm("mov.b64 {%0, %1}, %2;" : "=r"(lo), "=r"(hi) : "l"(v));
    return __uint_as_float(lo) + __uint_as_float(hi);
}

// ---------------- K1a/K1b: column norms -------------------------------------
__global__ void k_part(const float* __restrict__ x) {
    int p = blockIdx.x * 256 + threadIdx.x;
    int b = blockIdx.y;
    int z = blockIdx.z;
    const float* base = x + ((size_t)b * CH + (size_t)z * (CH / NSPLIT)) * HW + p;
    float s = 0.f;
#pragma unroll 8
    for (int c = 0; c < CH / NSPLIT; c++) {
        float v = base[(size_t)c * HW];
        s += v * v;
    }
    g_part[z][b * HW + p] = s;
}
__global__ void k_invall() {
    int i = blockIdx.x * 256 + threadIdx.x;
    float s = g_part[0][i] + g_part[1][i] + g_part[2][i] + g_part[3][i];
    g_n2[i] = s;
    g_invall[i] = 1.f / (sqrtf(s) + EPSF);
}

// ---------------- K2: setup --------------------------------------------------
__global__ void k_setup(const int* __restrict__ np, const int* __restrict__ mp) {
    int t = threadIdx.x;  // 1024, 1 block
    for (int p = t; p < HW; p += 1024) g_imask[p] = -1;
    __syncthreads();
    g_imask[mp[t]] = t;
    for (int i = t; i < BATCH * NMASK; i += 1024) g_packed[i] = 0ull;
    for (int i = t; i < BATCH * NMASK; i += 1024) {
        int b = i / NMASK;
        g_invm[i] = g_invall[b * HW + mp[i % NMASK]];
    }
    for (int j = t; j < BATCH * NCTX; j += 1024) {
        int b = j / NCTX;
        g_invc[j] = g_invall[b * HW + np[j % NCTX]];
    }
}

// ---------------- K3: gather A/B, K-major ------------------------------------
__global__ void k_gather(const float* __restrict__ x,
                         const int* __restrict__ np, const int* __restrict__ mp) {
    int k = blockIdx.x;
    int b = blockIdx.y;
    int t = threadIdx.x;        // 1024
    const float* row = x + ((size_t)b * CH + k) * HW;
    g_Am[((size_t)b * CH + k) * NMASK + t] = row[mp[t]];
#pragma unroll
    for (int j = t; j < NCTX; j += 1024)
        g_Bn[((size_t)b * CH + k) * NCTX + j] = row[np[j]];
}

// ---------------- K4: fp32 GEMM (R13 config: 2-stage cp.async, f32x2) -------
#define BM 128
#define BN 128
#define BK 16
#define NT (CH / BK)

__global__ void __launch_bounds__(256, 2) k_gemm() {
    __shared__ __align__(16) float As[2][BK][BM];
    __shared__ __align__(16) float Bs[2][BK][BN];

    int b  = blockIdx.z;
    int i0 = blockIdx.y * BM;
    int j0 = blockIdx.x * BN;
    int tid = threadIdx.x;
    int tx = tid & 15, ty = tid >> 4;
    int cA = tx * 4;

    const float* A  = g_Am + (size_t)b * CH * NMASK + i0;
    const float* Bp = g_Bn + (size_t)b * CH * NCTX  + j0;

    unsigned long long acc[8][4];
#pragma unroll
    for (int r = 0; r < 8; r++)
#pragma unroll
        for (int q = 0; q < 4; q++) acc[r][q] = 0ull;

#define COPY_TILE(t)                                                          \
    do {                                                                      \
        int s_ = (t) & 1;                                                     \
        const float* ga = A  + (size_t)((t) * BK + ty) * NMASK + cA;          \
        const float* gb = Bp + (size_t)((t) * BK + ty) * NCTX  + cA;          \
        cp16(&As[s_][ty][cA],      ga);                                       \
        cp16(&As[s_][ty][64 + cA], ga + 64);                                  \
        cp16(&Bs[s_][ty][cA],      gb);                                       \
        cp16(&Bs[s_][ty][64 + cA], gb + 64);                                  \
        asm volatile("cp.async.commit_group;\n");                             \
    } while (0)

    COPY_TILE(0);
    COPY_TILE(1);

#pragma unroll 1
    for (int t = 0; t < NT; t++) {
        if (t < NT - 1) asm volatile("cp.async.wait_group 1;\n");
        else            asm volatile("cp.async.wait_group 0;\n");
        __syncthreads();
        int s = t & 1;
#pragma unroll
        for (int kk = 0; kk < BK; kk++) {
            float4 a0 = *(const float4*)&As[s][kk][ty * 4];
            float4 a1 = *(const float4*)&As[s][kk][64 + ty * 4];
            ulonglong2 bv0 = *(const ulonglong2*)&Bs[s][kk][tx * 4];
            ulonglong2 bv1 = *(const ulonglong2*)&Bs[s][kk][64 + tx * 4];
            float ar[8] = {a0.x, a0.y, a0.z, a0.w, a1.x, a1.y, a1.z, a1.w};
            unsigned long long bq[4] = {bv0.x, bv0.y, bv1.x, bv1.y};
#pragma unroll
            for (int r = 0; r < 8; r++) {
                unsigned long long a2;
                asm("mov.b64 %0, {%1, %1};" : "=l"(a2) : "r"(__float_as_uint(ar[r])));
#pragma unroll
                for (int q = 0; q < 4; q++)
                    asm("fma.rn.f32x2 %0, %1, %2, %0;"
                        : "+l"(acc[r][q]) : "l"(a2), "l"(bq[q]));
            }
        }
        __syncthreads();
        if (t + 2 < NT) COPY_TILE(t + 2);
    }

    float invc[8];
#pragma unroll
    for (int g = 0; g < 2; g++)
#pragma unroll
        for (int e = 0; e < 4; e++)
            invc[g * 4 + e] = g_invc[b * NCTX + j0 + g * 64 + tx * 4 + e];

#pragma unroll
    for (int r = 0; r < 8; r++) {
        int irow = (r < 4) ? (ty * 4 + r) : (64 + ty * 4 + (r - 4));
        unsigned long long bp = 0ull;
#pragma unroll
        for (int q = 0; q < 4; q++) {
            float lo = __uint_as_float((unsigned)acc[r][q]);
            float hi = __uint_as_float((unsigned)(acc[r][q] >> 32));
            float v0 = lo * invc[q * 2];
            float v1 = hi * invc[q * 2 + 1];
            int jg = j0 + ((q >> 1) * 64) + tx * 4 + (q & 1) * 2;
            unsigned long long p0 = ((unsigned long long)ford(v0) << 32) | (unsigned)(~(unsigned)jg);
            unsigned long long p1 = ((unsigned long long)ford(v1) << 32) | (unsigned)(~(unsigned)(jg + 1));
            if (p0 > bp) bp = p0;
            if (p1 > bp) bp = p1;
        }
#pragma unroll
        for (int o = 1; o < 16; o <<= 1) {
            unsigned long long other = __shfl_xor_sync(0xffffffffu, bp, o);
            if (other > bp) bp = other;
        }
        if (tx == 0) atomicMax(&g_packed[b * NMASK + i0 + irow], bp);
    }
}

// ---------------- K5: finalize pick + gather + |best|^2 ----------------------
__global__ void k_finalize(const int* __restrict__ np) {
    int i = blockIdx.x;
    int b = blockIdx.y;
    int t = threadIdx.x;  // 256
    __shared__ int s_j;
    __shared__ float s_invm;
    if (t == 0) {
        unsigned long long pk = g_packed[b * NMASK + i];
        unsigned j  = ~(unsigned)pk;
        unsigned ov = (unsigned)(pk >> 32);
        unsigned fb = (ov & 0x80000000u) ? (ov & 0x7fffffffu) : ~ov;
        float val = __uint_as_float(fb);
        float im  = g_invm[b * NMASK + i];
        g_maxc[b * NMASK + i] = val * im;
        g_bn2[b * NMASK + i] = g_n2[b * HW + np[j]];
        s_j = (int)j;
        s_invm = im;
    }
    __syncthreads();
    int jj = s_j;
    float im = s_invm;
    const float* Am = g_Am + (size_t)b * CH * NMASK;
    const float* Bn = g_Bn + (size_t)b * CH * NCTX;
    size_t o = ((size_t)b * NMASK + i) * CH;
#pragma unroll
    for (int c = t; c < CH; c += 256) {
        g_best[o + c] = Bn[(size_t)c * NCTX + jj];
        g_mskn[o + c] = Am[(size_t)c * NMASK + i] * im;
    }
}

// ---------------- K6: scan v6 — f32x2-packed consumer math -------------------
#define NRING 16
#define NG (NMASK / 4)

struct ScanState { float s1, rnd; };

__device__ __forceinline__ void scan_step(
    int i, float mx, float bn2, unsigned long long* q2, ScanState& st,
    const float (*ring)[2][CH], float* GE, int lane)
{
    int s = i & (NRING - 1);
    unsigned long long mn2[8], bs2[8];
#pragma unroll
    for (int u = 0; u < 4; u++) {
        ulonglong2 a = *(const ulonglong2*)&ring[s][0][u * 128 + lane * 4];
        mn2[2 * u] = a.x; mn2[2 * u + 1] = a.y;
        ulonglong2 c = *(const ulonglong2*)&ring[s][1][u * 128 + lane * 4];
        bs2[2 * u] = c.x; bs2[2 * u + 1] = c.y;
    }
    // dual dot via packed pairs: (s2 even|odd), (c even|odd)
    unsigned long long as_[4], ac_[4];
#pragma unroll
    for (int j = 0; j < 4; j++) {
        as_[j] = mul2(mn2[j], q2[j]);
        ac_[j] = mul2(bs2[j], q2[j]);
    }
#pragma unroll
    for (int j = 4; j < 8; j++) {
        as_[j - 4] = fma2(mn2[j], q2[j], as_[j - 4]);
        ac_[j - 4] = fma2(bs2[j], q2[j], ac_[j - 4]);
    }
    as_[0] = add2(as_[0], as_[2]); as_[1] = add2(as_[1], as_[3]);
    ac_[0] = add2(ac_[0], ac_[2]); ac_[1] = add2(ac_[1], ac_[3]);
    as_[0] = add2(as_[0], as_[1]);
    ac_[0] = add2(ac_[0], ac_[1]);
    float s2 = hsum2(as_[0]);
    float c  = hsum2(ac_[0]);
#pragma unroll
    for (int o = 16; o; o >>= 1) {
        s2 += __shfl_xor_sync(0xffffffffu, s2, o);
        c  += __shfl_xor_sync(0xffffffffu, c,  o);
    }
    float s2p = fmaxf(s2, 0.f);
    float d   = s2p * st.rnd;
    float T   = d + mx + EPSF;
    float rT  = frcp(T);
    float w1 = d * rT, w2 = mx * rT;
    unsigned long long w1d = dup2(w1), w2d = dup2(w2);
#pragma unroll
    for (int j = 0; j < 8; j++)
        q2[j] = fma2(w1d, q2[j], mul2(w2d, bs2[j]));
    float* ge = GE + (size_t)i * CH + lane * 16;
#pragma unroll
    for (int u = 0; u < 4; u++) {
        ulonglong2 w;
        w.x = q2[2 * u]; w.y = q2[2 * u + 1];
        *(ulonglong2*)(ge + u * 4) = w;
    }
    float aa = w1 * w1, ab = w1 * w2, bb = w2 * w2;
    st.s1 = __fmaf_rn(aa, st.s1, __fmaf_rn(2.f * ab, c, bb * bn2));
    float rs  = (st.s1 > 0.f) ? frsq(st.s1) : 0.f;
    float nrm = st.s1 * rs;
    st.rnd = frcp(nrm + EPSF);
}

__global__ void __launch_bounds__(64, 1) k_scan() {
    __shared__ __align__(16) float ring[NRING][2][CH];   // 64KB
    __shared__ int rflag, cdone;

    int b = blockIdx.x;
    int warp = threadIdx.x >> 5;
    int lane = threadIdx.x & 31;

    const float* MN  = g_mskn + (size_t)b * NMASK * CH;
    const float* BS  = g_best + (size_t)b * NMASK * CH;
    float*       GE  = g_gen  + (size_t)b * NMASK * CH;
    const float* MX  = g_maxc + b * NMASK;
    const float* BN2 = g_bn2  + b * NMASK;

    if (threadIdx.x == 0) { rflag = -1; cdone = -1; }
    __syncthreads();

#define PRE(i, s)                                                             \
    do {                                                                      \
        const float* pm = MN + (size_t)(i) * CH + lane * 16;                  \
        const float* pb = BS + (size_t)(i) * CH + lane * 16;                  \
        cp16(&ring[s][0][0 * 128 + lane * 4], pm);                            \
        cp16(&ring[s][0][1 * 128 + lane * 4], pm + 4);                        \
        cp16(&ring[s][0][2 * 128 + lane * 4], pm + 8);                        \
        cp16(&ring[s][0][3 * 128 + lane * 4], pm + 12);                       \
        cp16(&ring[s][1][0 * 128 + lane * 4], pb);                            \
        cp16(&ring[s][1][1 * 128 + lane * 4], pb + 4);                        \
        cp16(&ring[s][1][2 * 128 + lane * 4], pb + 8);                        \
        cp16(&ring[s][1][3 * 128 + lane * 4], pb + 12);                       \
    } while (0)

    if (warp == 1) {
        // producer
#pragma unroll
        for (int g = 0; g < 4; g++) {
#pragma unroll
            for (int k = 0; k < 4; k++) PRE(4 * g + k, (4 * g + k) & (NRING - 1));
            asm volatile("cp.async.commit_group;\n");
        }
#pragma unroll 1
        for (int g = 0; g < NG; g++) {
            int rem = NG - 1 - g;
            if (rem >= 3)      asm volatile("cp.async.wait_group 3;\n");
            else if (rem == 2) asm volatile("cp.async.wait_group 2;\n");
            else if (rem == 1) asm volatile("cp.async.wait_group 1;\n");
            else               asm volatile("cp.async.wait_group 0;\n");
            __syncwarp();
            if (lane == 0) st_release_s32(&rflag, 4 * g + 3);
            if (g + 4 < NG) {
                while (ld_acquire_s32(&cdone) < 4 * g + 3) { }
                int s0 = 4 * (g + 4);
#pragma unroll
                for (int k = 0; k < 4; k++) PRE(s0 + k, (s0 + k) & (NRING - 1));
                asm volatile("cp.async.commit_group;\n");
            }
        }
    } else {
        // consumer
        unsigned long long q2[8];
#pragma unroll
        for (int e = 0; e < 8; e++) q2[e] = 0ull;
        ScanState st;
        st.s1 = 0.f;
        st.rnd = frcp(EPSF);
        int ready = -1;
        float4 mx4 = *(const float4*)MX;
        float4 b24 = *(const float4*)BN2;

#pragma unroll 1
        for (int g = 0; g < NG; g++) {
            int i0 = g * 4;
            if (ready < i0 + 3) {
                do { ready = ld_acquire_s32(&rflag); } while (ready < i0 + 3);
            }
            float4 mx4n = mx4, b24n = b24;
            if (g + 1 < NG) {
                mx4n = *(const float4*)(MX + i0 + 4);
                b24n = *(const float4*)(BN2 + i0 + 4);
            }
            scan_step(i0 + 0, mx4.x, b24.x, q2, st, ring, GE, lane);
            scan_step(i0 + 1, mx4.y, b24.y, q2, st, ring, GE, lane);
            scan_step(i0 + 2, mx4.z, b24.z, q2, st, ring, GE, lane);
            scan_step(i0 + 3, mx4.w, b24.w, q2, st, ring, GE, lane);
            mx4 = mx4n; b24 = b24n;
            __syncwarp();
            if (lane == 0) st_release_s32(&cdone, i0 + 3);
        }
    }
}

// ---------------- K7: assemble output ---------------------------------------
__global__ void k_out(const float* __restrict__ x, float* __restrict__ out) {
    int idx = blockIdx.x * 256 + threadIdx.x;
    int p = idx & (HW - 1);
    int c = (idx >> 12) & (CH - 1);
    int b = idx >> 21;
    int mi = g_imask[p];
    float v = (mi >= 0) ? g_gen[(((size_t)b * NMASK) + mi) * CH + c] : x[idx];
    out[idx] = v;
}

// ---------------- launch -----------------------------------------------------
extern "C" void kernel_launch(void* const* d_in, const int* in_sizes, int n_in,
                              void* d_out, int out_size) {
    const float* x  = (const float*)d_in[0];
    const int*   np = (const int*)d_in[2];
    const int*   mp = (const int*)d_in[3];
    float*       out = (float*)d_out;

    k_part    <<<dim3(HW / 256, BATCH, NSPLIT), 256>>>(x);
    k_invall  <<<BATCH * HW / 256, 256>>>();
    k_setup   <<<1, 1024>>>(np, mp);
    k_gather  <<<dim3(CH, BATCH), 1024>>>(x, np, mp);
    k_gemm    <<<dim3(NCTX / BN, NMASK / BM, BATCH), 256>>>();
    k_finalize<<<dim3(NMASK, BATCH), 256>>>(np);
    k_scan    <<<BATCH, 64>>>();
    k_out     <<<(BATCH * CH * HW) / 256, 256>>>(x, out);
}

// round 17
// speedup vs baseline: 1.4893x; 1.3445x over previous
#include <cuda_runtime.h>

#define BATCH 8
#define HW    4096
#define CH    512
#define NMASK 1024
#define NCTX  3072
#define EPSF  1e-8f
#define NSPLIT 4
#define NSEG  8
#define SEG   (NMASK / NSEG)      // 128 steps per segment

// ---------------- scratch ----------------------------------------------------
__device__ float g_Am[BATCH * CH * NMASK];            // [b][k][i]
__device__ float g_Bn[BATCH * CH * NCTX];             // [b][k][j]
__device__ float g_best[BATCH * NMASK * CH];
__device__ float g_mskn[BATCH * NMASK * CH];
__device__ float g_gen[BATCH * NMASK * CH];
__device__ float g_part[NSPLIT][BATCH * HW];
__device__ float g_invall[BATCH * HW];
__device__ float g_n2[BATCH * HW];
__device__ float g_invc[BATCH * NCTX];
__device__ float g_invm[BATCH * NMASK];
__device__ float g_maxc[BATCH * NMASK];
__device__ float g_bn2[BATCH * NMASK];
__device__ float g_qseg[BATCH][NSEG][CH];             // segment-end q
__device__ float g_s1seg[BATCH][NSEG];                // segment-end |q|^2
__device__ unsigned long long g_packed[BATCH * NMASK];
__device__ int   g_imask[HW];

// ---------------- helpers ----------------------------------------------------
__device__ __forceinline__ void cp16(void* sdst, const void* gsrc) {
    unsigned saddr = (unsigned)__cvta_generic_to_shared(sdst);
    asm volatile("cp.async.ca.shared.global [%0], [%1], 16;\n" :: "r"(saddr), "l"(gsrc));
}
__device__ __forceinline__ unsigned ford(float f) {
    unsigned u = __float_as_uint(f);
    return (u & 0x80000000u) ? ~u : (u | 0x80000000u);
}
__device__ __forceinline__ float frcp(float x) {
    float r; asm("rcp.approx.f32 %0, %1;" : "=f"(r) : "f"(x)); return r;
}
__device__ __forceinline__ float frsq(float x) {
    float r; asm("rsqrt.approx.f32 %0, %1;" : "=f"(r) : "f"(x)); return r;
}
__device__ __forceinline__ void st_release_s32(volatile int* p, int v) {
    unsigned a = (unsigned)__cvta_generic_to_shared((void*)p);
    asm volatile("st.release.cta.shared.b32 [%0], %1;" :: "r"(a), "r"(v) : "memory");
}
__device__ __forceinline__ int ld_acquire_s32(volatile int* p) {
    unsigned a = (unsigned)__cvta_generic_to_shared((void*)p);
    int v;
    asm volatile("ld.acquire.cta.shared.b32 %0, [%1];" : "=r"(v) : "r"(a) : "memory");
    return v;
}

// ---------------- K1a/K1b: column norms -------------------------------------
__global__ void k_part(const float* __restrict__ x) {
    int p = blockIdx.x * 256 + threadIdx.x;
    int b = blockIdx.y;
    int z = blockIdx.z;
    const float* base = x + ((size_t)b * CH + (size_t)z * (CH / NSPLIT)) * HW + p;
    float s = 0.f;
#pragma unroll 8
    for (int c = 0; c < CH / NSPLIT; c++) {
        float v = base[(size_t)c * HW];
        s += v * v;
    }
    g_part[z][b * HW + p] = s;
}
__global__ void k_invall() {
    int i = blockIdx.x * 256 + threadIdx.x;
    float s = g_part[0][i] + g_part[1][i] + g_part[2][i] + g_part[3][i];
    g_n2[i] = s;
    g_invall[i] = 1.f / (sqrtf(s) + EPSF);
}

// ---------------- K2: setup --------------------------------------------------
__global__ void k_setup(const int* __restrict__ np, const int* __restrict__ mp) {
    int t = threadIdx.x;  // 1024, 1 block
    for (int p = t; p < HW; p += 1024) g_imask[p] = -1;
    __syncthreads();
    g_imask[mp[t]] = t;
    for (int i = t; i < BATCH * NMASK; i += 1024) g_packed[i] = 0ull;
    for (int i = t; i < BATCH * NMASK; i += 1024) {
        int b = i / NMASK;
        g_invm[i] = g_invall[b * HW + mp[i % NMASK]];
    }
    for (int j = t; j < BATCH * NCTX; j += 1024) {
        int b = j / NCTX;
        g_invc[j] = g_invall[b * HW + np[j % NCTX]];
    }
}

// ---------------- K3: gather A/B, K-major ------------------------------------
__global__ void k_gather(const float* __restrict__ x,
                         const int* __restrict__ np, const int* __restrict__ mp) {
    int k = blockIdx.x;
    int b = blockIdx.y;
    int t = threadIdx.x;        // 1024
    const float* row = x + ((size_t)b * CH + k) * HW;
    g_Am[((size_t)b * CH + k) * NMASK + t] = row[mp[t]];
#pragma unroll
    for (int j = t; j < NCTX; j += 1024)
        g_Bn[((size_t)b * CH + k) * NCTX + j] = row[np[j]];
}

// ---------------- K4: fp32 GEMM (2-stage cp.async, f32x2 FFMA) --------------
#define BM 128
#define BN 128
#define BK 16
#define NT (CH / BK)

__global__ void __launch_bounds__(256, 2) k_gemm() {
    __shared__ __align__(16) float As[2][BK][BM];
    __shared__ __align__(16) float Bs[2][BK][BN];

    int b  = blockIdx.z;
    int i0 = blockIdx.y * BM;
    int j0 = blockIdx.x * BN;
    int tid = threadIdx.x;
    int tx = tid & 15, ty = tid >> 4;
    int cA = tx * 4;

    const float* A  = g_Am + (size_t)b * CH * NMASK + i0;
    const float* Bp = g_Bn + (size_t)b * CH * NCTX  + j0;

    unsigned long long acc[8][4];
#pragma unroll
    for (int r = 0; r < 8; r++)
#pragma unroll
        for (int q = 0; q < 4; q++) acc[r][q] = 0ull;

#define COPY_TILE(t)                                                          \
    do {                                                                      \
        int s_ = (t) & 1;                                                     \
        const float* ga = A  + (size_t)((t) * BK + ty) * NMASK + cA;          \
        const float* gb = Bp + (size_t)((t) * BK + ty) * NCTX  + cA;          \
        cp16(&As[s_][ty][cA],      ga);                                       \
        cp16(&As[s_][ty][64 + cA], ga + 64);                                  \
        cp16(&Bs[s_][ty][cA],      gb);                                       \
        cp16(&Bs[s_][ty][64 + cA], gb + 64);                                  \
        asm volatile("cp.async.commit_group;\n");                             \
    } while (0)

    COPY_TILE(0);
    COPY_TILE(1);

#pragma unroll 1
    for (int t = 0; t < NT; t++) {
        if (t < NT - 1) asm volatile("cp.async.wait_group 1;\n");
        else            asm volatile("cp.async.wait_group 0;\n");
        __syncthreads();
        int s = t & 1;
#pragma unroll
        for (int kk = 0; kk < BK; kk++) {
            float4 a0 = *(const float4*)&As[s][kk][ty * 4];
            float4 a1 = *(const float4*)&As[s][kk][64 + ty * 4];
            ulonglong2 bv0 = *(const ulonglong2*)&Bs[s][kk][tx * 4];
            ulonglong2 bv1 = *(const ulonglong2*)&Bs[s][kk][64 + tx * 4];
            float ar[8] = {a0.x, a0.y, a0.z, a0.w, a1.x, a1.y, a1.z, a1.w};
            unsigned long long bq[4] = {bv0.x, bv0.y, bv1.x, bv1.y};
#pragma unroll
            for (int r = 0; r < 8; r++) {
                unsigned long long a2;
                asm("mov.b64 %0, {%1, %1};" : "=l"(a2) : "r"(__float_as_uint(ar[r])));
#pragma unroll
                for (int q = 0; q < 4; q++)
                    asm("fma.rn.f32x2 %0, %1, %2, %0;"
                        : "+l"(acc[r][q]) : "l"(a2), "l"(bq[q]));
            }
        }
        __syncthreads();
        if (t + 2 < NT) COPY_TILE(t + 2);
    }

    float invc[8];
#pragma unroll
    for (int g = 0; g < 2; g++)
#pragma unroll
        for (int e = 0; e < 4; e++)
            invc[g * 4 + e] = g_invc[b * NCTX + j0 + g * 64 + tx * 4 + e];

#pragma unroll
    for (int r = 0; r < 8; r++) {
        int irow = (r < 4) ? (ty * 4 + r) : (64 + ty * 4 + (r - 4));
        unsigned long long bp = 0ull;
#pragma unroll
        for (int q = 0; q < 4; q++) {
            float lo = __uint_as_float((unsigned)acc[r][q]);
            float hi = __uint_as_float((unsigned)(acc[r][q] >> 32));
            float v0 = lo * invc[q * 2];
            float v1 = hi * invc[q * 2 + 1];
            int jg = j0 + ((q >> 1) * 64) + tx * 4 + (q & 1) * 2;
            unsigned long long p0 = ((unsigned long long)ford(v0) << 32) | (unsigned)(~(unsigned)jg);
            unsigned long long p1 = ((unsigned long long)ford(v1) << 32) | (unsigned)(~(unsigned)(jg + 1));
            if (p0 > bp) bp = p0;
            if (p1 > bp) bp = p1;
        }
#pragma unroll
        for (int o = 1; o < 16; o <<= 1) {
            unsigned long long other = __shfl_xor_sync(0xffffffffu, bp, o);
            if (other > bp) bp = other;
        }
        if (tx == 0) atomicMax(&g_packed[b * NMASK + i0 + irow], bp);
    }
}

// ---------------- K5: finalize pick + gather + |best|^2 ----------------------
__global__ void k_finalize(const int* __restrict__ np) {
    int i = blockIdx.x;
    int b = blockIdx.y;
    int t = threadIdx.x;  // 256
    __shared__ int s_j;
    __shared__ float s_invm;
    if (t == 0) {
        unsigned long long pk = g_packed[b * NMASK + i];
        unsigned j  = ~(unsigned)pk;
        unsigned ov = (unsigned)(pk >> 32);
        unsigned fb = (ov & 0x80000000u) ? (ov & 0x7fffffffu) : ~ov;
        float val = __uint_as_float(fb);
        float im  = g_invm[b * NMASK + i];
        g_maxc[b * NMASK + i] = val * im;
        g_bn2[b * NMASK + i] = g_n2[b * HW + np[j]];
        s_j = (int)j;
        s_invm = im;
    }
    __syncthreads();
    int jj = s_j;
    float im = s_invm;
    const float* Am = g_Am + (size_t)b * CH * NMASK;
    const float* Bn = g_Bn + (size_t)b * CH * NCTX;
    size_t o = ((size_t)b * NMASK + i) * CH;
#pragma unroll
    for (int c = t; c < CH; c += 256) {
        g_best[o + c] = Bn[(size_t)c * NCTX + jj];
        g_mskn[o + c] = Am[(size_t)c * NMASK + i] * im;
    }
}

// ---------------- K6: segmented contraction scan -----------------------------
// Phase 1: 64 parallel chains (8 seg x 8 batch), q0=0 guess, 128 steps, store
//          segment-end (q, s1). Contraction w1<1 makes end states correct to
//          ~Prod(w1) <= ~1e-6 (segment 0 exact).
// Phase 2: rerun each segment from predecessor's end state; write outputs.
#define NRING 16
#define NGSEG (SEG / 4)            // 32 groups per segment

struct ScanState { float s1, rnd; };

template <int WRITE>
__device__ __forceinline__ void scan_step(
    int li, float mx, float bn2, float* q, ScanState& st,
    const float (*ring)[2][CH], float* GE, int lane)
{
    int s = li & (NRING - 1);
    float mn[16], bs[16];
#pragma unroll
    for (int u = 0; u < 4; u++) {
        float4 a = *(const float4*)&ring[s][0][u * 128 + lane * 4];
        mn[u*4+0]=a.x; mn[u*4+1]=a.y; mn[u*4+2]=a.z; mn[u*4+3]=a.w;
        float4 c = *(const float4*)&ring[s][1][u * 128 + lane * 4];
        bs[u*4+0]=c.x; bs[u*4+1]=c.y; bs[u*4+2]=c.z; bs[u*4+3]=c.w;
    }
    float p2[8], pc[8];
#pragma unroll
    for (int e = 0; e < 8; e++) {
        p2[e] = __fmaf_rn(mn[e], q[e], mn[e + 8] * q[e + 8]);
        pc[e] = __fmaf_rn(bs[e], q[e], bs[e + 8] * q[e + 8]);
    }
#pragma unroll
    for (int w = 4; w; w >>= 1)
#pragma unroll
        for (int e = 0; e < w; e++) { p2[e] += p2[e + w]; pc[e] += pc[e + w]; }
    float s2 = p2[0], c = pc[0];
#pragma unroll
    for (int o = 16; o; o >>= 1) {
        s2 += __shfl_xor_sync(0xffffffffu, s2, o);
        c  += __shfl_xor_sync(0xffffffffu, c,  o);
    }
    float s2p = fmaxf(s2, 0.f);
    float d   = s2p * st.rnd;
    float T   = d + mx + EPSF;
    float rT  = frcp(T);
    float w1 = d * rT, w2 = mx * rT;
#pragma unroll
    for (int e = 0; e < 16; e++) q[e] = __fmaf_rn(w1, q[e], w2 * bs[e]);
    if (WRITE) {
        float* ge = GE + (size_t)li * CH + lane * 16;
#pragma unroll
        for (int u = 0; u < 4; u++) {
            float4 w;
            w.x = q[u*4+0]; w.y = q[u*4+1]; w.z = q[u*4+2]; w.w = q[u*4+3];
            *(float4*)(ge + u * 4) = w;
        }
    }
    float aa = w1 * w1, ab = w1 * w2, bb = w2 * w2;
    st.s1 = __fmaf_rn(aa, st.s1, __fmaf_rn(2.f * ab, c, bb * bn2));
    float rs  = (st.s1 > 0.f) ? frsq(st.s1) : 0.f;
    float nrm = st.s1 * rs;
    st.rnd = frcp(nrm + EPSF);
}

template <int PHASE>
__global__ void __launch_bounds__(64, 1) k_scan() {
    __shared__ __align__(16) float ring[NRING][2][CH];   // 64KB
    __shared__ int rflag, cdone;

    int seg = blockIdx.x;
    int b   = blockIdx.y;
    int base = seg * SEG;
    int warp = threadIdx.x >> 5;
    int lane = threadIdx.x & 31;

    const float* MN  = g_mskn + ((size_t)b * NMASK + base) * CH;
    const float* BS  = g_best + ((size_t)b * NMASK + base) * CH;
    float*       GE  = g_gen  + ((size_t)b * NMASK + base) * CH;
    const float* MX  = g_maxc + b * NMASK + base;
    const float* BN2 = g_bn2  + b * NMASK + base;

    if (threadIdx.x == 0) { rflag = -1; cdone = -1; }
    __syncthreads();

#define PRE(i, s)                                                             \
    do {                                                                      \
        const float* pm = MN + (size_t)(i) * CH + lane * 16;                  \
        const float* pb = BS + (size_t)(i) * CH + lane * 16;                  \
        cp16(&ring[s][0][0 * 128 + lane * 4], pm);                            \
        cp16(&ring[s][0][1 * 128 + lane * 4], pm + 4);                        \
        cp16(&ring[s][0][2 * 128 + lane * 4], pm + 8);                        \
        cp16(&ring[s][0][3 * 128 + lane * 4], pm + 12);                       \
        cp16(&ring[s][1][0 * 128 + lane * 4], pb);                            \
        cp16(&ring[s][1][1 * 128 + lane * 4], pb + 4);                        \
        cp16(&ring[s][1][2 * 128 + lane * 4], pb + 8);                        \
        cp16(&ring[s][1][3 * 128 + lane * 4], pb + 12);                       \
    } while (0)

    if (warp == 1) {
        // producer
#pragma unroll
        for (int g = 0; g < 4; g++) {
#pragma unroll
            for (int k = 0; k < 4; k++) PRE(4 * g + k, (4 * g + k) & (NRING - 1));
            asm volatile("cp.async.commit_group;\n");
        }
#pragma unroll 1
        for (int g = 0; g < NGSEG; g++) {
            int rem = NGSEG - 1 - g;
            if (rem >= 3)      asm volatile("cp.async.wait_group 3;\n");
            else if (rem == 2) asm volatile("cp.async.wait_group 2;\n");
            else if (rem == 1) asm volatile("cp.async.wait_group 1;\n");
            else               asm volatile("cp.async.wait_group 0;\n");
            __syncwarp();
            if (lane == 0) st_release_s32(&rflag, 4 * g + 3);
            if (g + 4 < NGSEG) {
                while (ld_acquire_s32(&cdone) < 4 * g + 3) { }
                int s0 = 4 * (g + 4);
#pragma unroll
                for (int k = 0; k < 4; k++) PRE(s0 + k, (s0 + k) & (NRING - 1));
                asm volatile("cp.async.commit_group;\n");
            }
        }
    } else {
        // consumer
        float q[16];
        ScanState st;
        if (PHASE == 2 && seg > 0) {
            const float* qs = &g_qseg[b][seg - 1][lane * 16];
#pragma unroll
            for (int u = 0; u < 4; u++) {
                float4 v = *(const float4*)(qs + u * 4);
                q[u*4+0]=v.x; q[u*4+1]=v.y; q[u*4+2]=v.z; q[u*4+3]=v.w;
            }
            st.s1 = g_s1seg[b][seg - 1];
            float rs  = (st.s1 > 0.f) ? frsq(st.s1) : 0.f;
            st.rnd = frcp(st.s1 * rs + EPSF);
        } else {
#pragma unroll
            for (int e = 0; e < 16; e++) q[e] = 0.f;
            st.s1 = 0.f;
            st.rnd = frcp(EPSF);
        }
        int ready = -1;
        float4 mx4 = *(const float4*)MX;
        float4 b24 = *(const float4*)BN2;

#pragma unroll 1
        for (int g = 0; g < NGSEG; g++) {
            int i0 = g * 4;
            if (ready < i0 + 3) {
                do { ready = ld_acquire_s32(&rflag); } while (ready < i0 + 3);
            }
            float4 mx4n = mx4, b24n = b24;
            if (g + 1 < NGSEG) {
                mx4n = *(const float4*)(MX + i0 + 4);
                b24n = *(const float4*)(BN2 + i0 + 4);
            }
            scan_step<PHASE == 2>(i0 + 0, mx4.x, b24.x, q, st, ring, GE, lane);
            scan_step<PHASE == 2>(i0 + 1, mx4.y, b24.y, q, st, ring, GE, lane);
            scan_step<PHASE == 2>(i0 + 2, mx4.z, b24.z, q, st, ring, GE, lane);
            scan_step<PHASE == 2>(i0 + 3, mx4.w, b24.w, q, st, ring, GE, lane);
            mx4 = mx4n; b24 = b24n;
            __syncwarp();
            if (lane == 0) st_release_s32(&cdone, i0 + 3);
        }

        if (PHASE == 1) {
            float* qs = &g_qseg[b][seg][lane * 16];
#pragma unroll
            for (int u = 0; u < 4; u++) {
                float4 v;
                v.x = q[u*4+0]; v.y = q[u*4+1]; v.z = q[u*4+2]; v.w = q[u*4+3];
                *(float4*)(qs + u * 4) = v;
            }
            if (lane == 0) g_s1seg[b][seg] = st.s1;
        }
    }
}

// ---------------- K7: assemble output ---------------------------------------
__global__ void k_out(const float* __restrict__ x, float* __restrict__ out) {
    int idx = blockIdx.x * 256 + threadIdx.x;
    int p = idx & (HW - 1);
    int c = (idx >> 12) & (CH - 1);
    int b = idx >> 21;
    int mi = g_imask[p];
    float v = (mi >= 0) ? g_gen[(((size_t)b * NMASK) + mi) * CH + c] : x[idx];
    out[idx] = v;
}

// ---------------- launch -----------------------------------------------------
extern "C" void kernel_launch(void* const* d_in, const int* in_sizes, int n_in,
                              void* d_out, int out_size) {
    const float* x  = (const float*)d_in[0];
    const int*   np = (const int*)d_in[2];
    const int*   mp = (const int*)d_in[3];
    float*       out = (float*)d_out;

    k_part    <<<dim3(HW / 256, BATCH, NSPLIT), 256>>>(x);
    k_invall  <<<BATCH * HW / 256, 256>>>();
    k_setup   <<<1, 1024>>>(np, mp);
    k_gather  <<<dim3(CH, BATCH), 1024>>>(x, np, mp);
    k_gemm    <<<dim3(NCTX / BN, NMASK / BM, BATCH), 256>>>();
    k_finalize<<<dim3(NMASK, BATCH), 256>>>(np);
    k_scan<1> <<<dim3(NSEG, BATCH), 64>>>();
    k_scan<2> <<<dim3(NSEG, BATCH), 64>>>();
    k_out     <<<(BATCH * CH * HW) / 256, 256>>>(x, out);
}